// round 7
// baseline (speedup 1.0000x reference)
#include <cuda_runtime.h>
#include <cuda_fp16.h>
#include <cstdint>

#define N_ITEMS_K 1000000
#define FEAT_K    256
#define BAG_K     128
#define N_BAGS_K  50000
#define TILE_K    64
#define N_TILES_K (N_ITEMS_K / TILE_K)   // 15625 exact
#define EPS_K     1e-5f

// ---------------- device scratch ----------------
__device__ float g_scratch[(size_t)N_BAGS_K * BAG_K + 2 * BAG_K];

// ---------------- shared memory layout (byte offsets) ----------------
// seg ids : [0, 256)
// b vec   : [512, 1024)
// x buf 0 : [1024, 66560)     64 rows x 1024 B fp32, slot-XOR swizzle
//           (also W_hi staging area at startup: 128 rows x 512 B swizzled)
// x buf 1 : [66560, 132096)
// h       : [132096, 165888)  64 x 132 f32
#define SM_SEG   0
#define SM_B     512
#define XBUF(b)  (1024 + (b) * 65536)
#define SM_H     132096
#define H_STRIDE 132
#define SMEM_DYN 165888

__device__ __forceinline__ uint32_t smem_u32(const void* p) {
    uint32_t a;
    asm("{ .reg .u64 t; cvta.to.shared.u64 t, %1; cvt.u32.u64 %0, t; }" : "=r"(a) : "l"(p));
    return a;
}

__device__ __forceinline__ void ldsm4(uint32_t* r, uint32_t addr) {
    asm volatile("ldmatrix.sync.aligned.m8n8.x4.shared.b16 {%0,%1,%2,%3}, [%4];"
                 : "=r"(r[0]), "=r"(r[1]), "=r"(r[2]), "=r"(r[3]) : "r"(addr));
}

__device__ __forceinline__ void mma16816(float* c, const uint32_t* a,
                                         uint32_t b0, uint32_t b1) {
    asm volatile(
        "mma.sync.aligned.m16n8k16.row.col.f32.f16.f16.f32 "
        "{%0,%1,%2,%3},{%4,%5,%6,%7},{%8,%9},{%0,%1,%2,%3};"
        : "+f"(c[0]), "+f"(c[1]), "+f"(c[2]), "+f"(c[3])
        : "r"(a[0]), "r"(a[1]), "r"(a[2]), "r"(a[3]), "r"(b0), "r"(b1));
}

__device__ __forceinline__ void cp_async16(uint32_t dst, const void* src) {
    asm volatile("cp.async.cg.shared.global [%0], [%1], 16;"
                 :: "r"(dst), "l"(src) : "memory");
}
#define CP_COMMIT() asm volatile("cp.async.commit_group;" ::: "memory")
#define CP_WAIT1()  asm volatile("cp.async.wait_group 1;" ::: "memory")

__device__ __forceinline__ void split2(float x, float y, uint32_t& hi, uint32_t& lo) {
    __half2 h, l;
    h.x = __float2half_rn(x);
    h.y = __float2half_rn(y);
    l.x = __float2half_rn(x - __half2float(h.x));
    l.y = __float2half_rn(y - __half2float(h.y));
    hi = *(uint32_t*)&h;
    lo = *(uint32_t*)&l;
}

// x smem offset for (buf, row, float-index f within 256)
__device__ __forceinline__ uint32_t xoff(int buf, int r, int f) {
    return (uint32_t)XBUF(buf) + (uint32_t)r * 1024u
         + ((((uint32_t)f >> 2) ^ ((uint32_t)r & 7u)) << 4)
         + ((uint32_t)f & 3u) * 4u;
}

__global__ void __launch_bounds__(512, 1)
fused_gemm_seg_kernel(const float* __restrict__ x, const float* __restrict__ W,
                      const float* __restrict__ bvec, const int* __restrict__ seg)
{
    extern __shared__ char sm[];
    const uint32_t sb = smem_u32(sm);
    const int tid  = threadIdx.x;
    const int lane = tid & 31;
    const int wid  = tid >> 5;

    int*   seg_s = (int*)(sm + SM_SEG);
    float* b_s   = (float*)(sm + SM_B);
    float* h_s   = (float*)(sm + SM_H);

    // warp tiling: 2 M-groups (32 rows) x 4 N-quarters (32 cols) x 2 K-halves
    const int mgrp = (wid >> 3) & 1;
    const int nq   = (wid >> 1) & 3;
    const int kh   = wid & 1;

    // fragment lane geometry
    const int g  = lane >> 2;
    const int tq = lane & 3;
    const int b_ln = ((lane >> 4) << 3) + (lane & 7);
    const int b_ku = (lane >> 3) & 1;
    const uint32_t b_base = (uint32_t)(nq * 32 + b_ln) * 512u;
    const uint32_t lane7  = (uint32_t)(lane & 7);
    const int R0 = mgrp * 32 + g;           // rows R0, R0+8, R0+16, R0+24

    // ---- one-time: stage W_hi fp16 into xbuf0, swizzled [n][512B] ----
    for (int idx = tid; idx < BAG_K * FEAT_K; idx += 512) {
        int n = idx >> 8, k = idx & 255;
        uint32_t off = (uint32_t)n * 512u
                     + ((uint32_t)((k >> 3) ^ (n & 7)) << 4)
                     + (uint32_t)(k & 7) * 2u;
        *(__half*)(sm + XBUF(0) + off) = __float2half_rn(W[idx]);
    }
    if (tid < BAG_K) b_s[tid] = bvec[tid];
    __syncthreads();

    // ---- persistent B fragments: this warp's 32 cols x its K half ----
    uint32_t Bp[8][2][4];
    #pragma unroll
    for (int s = 0; s < 8; s++) {
        const int sg = kh * 8 + s;
        const uint32_t bun = ((uint32_t)(2 * sg + b_ku) ^ lane7) << 4;
        ldsm4(Bp[s][0], sb + (uint32_t)XBUF(0) + b_base + bun);
        ldsm4(Bp[s][1], sb + (uint32_t)XBUF(0) + b_base + 8192u + bun);
    }
    __syncthreads();   // all B loads done before xbuf0 is overwritten

    const float4* xf4 = (const float4*)x;

    // ---- prologue: prefetch first tile into buf 0 ----
    {
        const int t0 = blockIdx.x;
        #pragma unroll
        for (int it = 0; it < 8; it++) {
            int gg = it * 512 + tid;            // 4096 float4 slots
            int row = gg >> 6, s = gg & 63;
            uint32_t dst = sb + (uint32_t)XBUF(0) + (uint32_t)row * 1024u
                         + ((((uint32_t)s) ^ ((uint32_t)row & 7u)) << 4);
            cp_async16(dst, xf4 + (size_t)(t0 * TILE_K + row) * 64 + s);
        }
        CP_COMMIT();
    }

    int buf = 0;
    for (int t = blockIdx.x; t < N_TILES_K; t += gridDim.x) {
        int segreg = 0;
        if (tid < TILE_K) segreg = seg[t * TILE_K + tid];

        // prefetch next tile into buf^1
        const int tn = t + gridDim.x;
        if (tn < N_TILES_K) {
            #pragma unroll
            for (int it = 0; it < 8; it++) {
                int gg = it * 512 + tid;
                int row = gg >> 6, s = gg & 63;
                uint32_t dst = sb + (uint32_t)XBUF(buf ^ 1) + (uint32_t)row * 1024u
                             + ((((uint32_t)s) ^ ((uint32_t)row & 7u)) << 4);
                cp_async16(dst, xf4 + (size_t)(tn * TILE_K + row) * 64 + s);
            }
        }
        CP_COMMIT();
        CP_WAIT1();
        __syncthreads();

        float acc[2][4][4];
        #pragma unroll
        for (int m = 0; m < 2; m++)
            #pragma unroll
            for (int n = 0; n < 4; n++)
                #pragma unroll
                for (int i = 0; i < 4; i++) acc[m][n][i] = 0.f;

        // ---- k-loop: 8 k-steps (this warp's K half), B from registers ----
        #pragma unroll
        for (int s = 0; s < 8; s++) {
            const int f0 = kh * 128 + s * 16 + 2 * tq;
            #pragma unroll
            for (int m = 0; m < 2; m++) {
                const int R = R0 + m * 16;
                float2 v0 = *(const float2*)(sm + xoff(buf, R,     f0));
                float2 v1 = *(const float2*)(sm + xoff(buf, R + 8, f0));
                float2 v2 = *(const float2*)(sm + xoff(buf, R,     f0 + 8));
                float2 v3 = *(const float2*)(sm + xoff(buf, R + 8, f0 + 8));
                uint32_t Ah[4], Al[4];
                split2(v0.x, v0.y, Ah[0], Al[0]);
                split2(v1.x, v1.y, Ah[1], Al[1]);
                split2(v2.x, v2.y, Ah[2], Al[2]);
                split2(v3.x, v3.y, Ah[3], Al[3]);

                mma16816(acc[m][0], Ah, Bp[s][0][0], Bp[s][0][1]);
                mma16816(acc[m][1], Ah, Bp[s][0][2], Bp[s][0][3]);
                mma16816(acc[m][2], Ah, Bp[s][1][0], Bp[s][1][1]);
                mma16816(acc[m][3], Ah, Bp[s][1][2], Bp[s][1][3]);
                mma16816(acc[m][0], Al, Bp[s][0][0], Bp[s][0][1]);
                mma16816(acc[m][1], Al, Bp[s][0][2], Bp[s][0][3]);
                mma16816(acc[m][2], Al, Bp[s][1][0], Bp[s][1][1]);
                mma16816(acc[m][3], Al, Bp[s][1][2], Bp[s][1][3]);
            }
        }

        // ---- epilogue: kh0 stores raw partial, kh1 adds + bias + relu ----
        const int c0 = nq * 32 + 2 * tq;
        if (kh == 0) {
            #pragma unroll
            for (int m = 0; m < 2; m++) {
                const int R = R0 + m * 16;
                #pragma unroll
                for (int n = 0; n < 4; n++) {
                    const int c = c0 + n * 8;
                    *(float2*)&h_s[(size_t)R * H_STRIDE + c] =
                        make_float2(acc[m][n][0], acc[m][n][1]);
                    *(float2*)&h_s[(size_t)(R + 8) * H_STRIDE + c] =
                        make_float2(acc[m][n][2], acc[m][n][3]);
                }
            }
        }
        __syncthreads();
        if (kh == 1) {
            #pragma unroll
            for (int m = 0; m < 2; m++) {
                const int R = R0 + m * 16;
                #pragma unroll
                for (int n = 0; n < 4; n++) {
                    const int c = c0 + n * 8;
                    const float b0 = b_s[c], b1 = b_s[c + 1];
                    float2 p0 = *(const float2*)&h_s[(size_t)R * H_STRIDE + c];
                    float2 p1 = *(const float2*)&h_s[(size_t)(R + 8) * H_STRIDE + c];
                    p0.x = fmaxf(p0.x + acc[m][n][0] + b0, 0.f);
                    p0.y = fmaxf(p0.y + acc[m][n][1] + b1, 0.f);
                    p1.x = fmaxf(p1.x + acc[m][n][2] + b0, 0.f);
                    p1.y = fmaxf(p1.y + acc[m][n][3] + b1, 0.f);
                    *(float2*)&h_s[(size_t)R * H_STRIDE + c]       = p0;
                    *(float2*)&h_s[(size_t)(R + 8) * H_STRIDE + c] = p1;
                }
            }
        }
        if (tid < TILE_K) seg_s[tid] = segreg;
        __syncthreads();

        // ---- segment reduce: 4 row-quarters x 128 columns ----
        {
            const int c  = tid & 127;
            const int r0 = (tid >> 7) * 16;
            float a = 0.f;
            int cur = seg_s[r0];
            #pragma unroll
            for (int r = r0; r < r0 + 16; r++) {
                int s = seg_s[r];
                if (s != cur) {
                    atomicAdd(&g_scratch[(size_t)cur * BAG_K + c], a);
                    a = 0.f;
                    cur = s;
                }
                a += h_s[r * H_STRIDE + c];
            }
            atomicAdd(&g_scratch[(size_t)cur * BAG_K + c], a);
        }
        __syncthreads();
        buf ^= 1;
    }
}

// ---- per-column batch stats over the 50k bag means ----
__global__ void __launch_bounds__(128) stats_kernel(const int* __restrict__ blen)
{
    const int c = threadIdx.x;
    float s = 0.f, ss = 0.f;
    for (int r = blockIdx.x; r < N_BAGS_K; r += gridDim.x) {
        float cnt = (float)max(blen[r], 1);
        float v = g_scratch[(size_t)r * BAG_K + c] / cnt;
        s += v;
        ss += v * v;
    }
    atomicAdd(&g_scratch[(size_t)N_BAGS_K * BAG_K + c], s);
    atomicAdd(&g_scratch[(size_t)N_BAGS_K * BAG_K + BAG_K + c], ss);
}

// ---- normalize ----
__global__ void __launch_bounds__(128) norm_kernel(const int* __restrict__ blen,
                                                   const float* __restrict__ gamma,
                                                   const float* __restrict__ beta,
                                                   float* __restrict__ out)
{
    const int c = threadIdx.x;
    const float inv_n = 1.f / (float)N_BAGS_K;
    float mean = g_scratch[(size_t)N_BAGS_K * BAG_K + c] * inv_n;
    float ex2  = g_scratch[(size_t)N_BAGS_K * BAG_K + BAG_K + c] * inv_n;
    float scale = rsqrtf(ex2 - mean * mean + EPS_K) * gamma[c];
    float shift = beta[c];
    for (int r = blockIdx.x; r < N_BAGS_K; r += gridDim.x) {
        float cnt = (float)max(blen[r], 1);
        float v = g_scratch[(size_t)r * BAG_K + c] / cnt;
        out[(size_t)r * BAG_K + c] = (v - mean) * scale + shift;
    }
}

extern "C" void kernel_launch(void* const* d_in, const int* in_sizes, int n_in,
                              void* d_out, int out_size)
{
    const float* x     = (const float*)d_in[0];
    const float* W     = (const float*)d_in[1];
    const float* bvec  = (const float*)d_in[2];
    const float* gamma = (const float*)d_in[3];
    const float* beta  = (const float*)d_in[4];
    const int*   seg   = (const int*)d_in[5];
    const int*   blen  = (const int*)d_in[6];
    float*       out   = (float*)d_out;

    (void)in_sizes; (void)n_in; (void)out_size;

    void* scratch = nullptr;
    cudaGetSymbolAddress(&scratch, g_scratch);
    cudaMemsetAsync(scratch, 0,
                    sizeof(float) * ((size_t)N_BAGS_K * BAG_K + 2 * BAG_K), 0);

    int dev = 0, nsm = 148;
    cudaGetDevice(&dev);
    cudaDeviceGetAttribute(&nsm, cudaDevAttrMultiProcessorCount, dev);

    cudaFuncSetAttribute(fused_gemm_seg_kernel,
                         cudaFuncAttributeMaxDynamicSharedMemorySize, SMEM_DYN);
    fused_gemm_seg_kernel<<<nsm, 512, SMEM_DYN>>>(x, W, bvec, seg);
    stats_kernel<<<1024, 128>>>(blen);
    norm_kernel<<<2048, 128>>>(blen, gamma, beta, out);
}

// round 8
// speedup vs baseline: 1.2257x; 1.2257x over previous
#include <cuda_runtime.h>
#include <cuda_fp16.h>
#include <cstdint>

#define N_ITEMS_K 1000000
#define FEAT_K    256
#define BAG_K     128
#define N_BAGS_K  50000
#define TILE_K    128
#define N_TILES_K ((N_ITEMS_K + TILE_K - 1) / TILE_K)   // 7813 (last tile 64 rows)
#define EPS_K     1e-5f

// ---------------- device scratch ----------------
__device__ float g_scratch[(size_t)N_BAGS_K * BAG_K + 2 * BAG_K];

// ---------------- shared memory layout (byte offsets) ----------------
// seg ids : [0, 512)
// b vec   : [512, 1024)
// W fp16  : [1024, 66560)     128 rows x 512 B, K-permuted + XOR swizzle
// buf0    : [66560, 132096)   128 rows x 512 B fp32 (K-half), XOR swizzle
// buf1    : [132096, 197632)  (h fp32 128x512B aliases buf1 in epilogue)
#define SM_SEG   0
#define SM_B     512
#define SM_W     1024
#define XBUF(b)  (66560 + (b) * 65536)
#define SM_HB    132096
#define SMEM_DYN 197632

__device__ __forceinline__ uint32_t smem_u32(const void* p) {
    uint32_t a;
    asm("{ .reg .u64 t; cvta.to.shared.u64 t, %1; cvt.u32.u64 %0, t; }" : "=r"(a) : "l"(p));
    return a;
}

__device__ __forceinline__ void ldsm4(uint32_t* r, uint32_t addr) {
    asm volatile("ldmatrix.sync.aligned.m8n8.x4.shared.b16 {%0,%1,%2,%3}, [%4];"
                 : "=r"(r[0]), "=r"(r[1]), "=r"(r[2]), "=r"(r[3]) : "r"(addr));
}

__device__ __forceinline__ void mma16816(float* c, const uint32_t* a,
                                         uint32_t b0, uint32_t b1) {
    asm volatile(
        "mma.sync.aligned.m16n8k16.row.col.f32.f16.f16.f32 "
        "{%0,%1,%2,%3},{%4,%5,%6,%7},{%8,%9},{%0,%1,%2,%3};"
        : "+f"(c[0]), "+f"(c[1]), "+f"(c[2]), "+f"(c[3])
        : "r"(a[0]), "r"(a[1]), "r"(a[2]), "r"(a[3]), "r"(b0), "r"(b1));
}

__device__ __forceinline__ void cp_async16z(uint32_t dst, const void* src, bool pred) {
    int sz = pred ? 16 : 0;
    asm volatile("cp.async.cg.shared.global [%0], [%1], 16, %2;"
                 :: "r"(dst), "l"(src), "r"(sz) : "memory");
}
#define CP_COMMIT() asm volatile("cp.async.commit_group;" ::: "memory")
#define CP_WAIT1()  asm volatile("cp.async.wait_group 1;" ::: "memory")

__device__ __forceinline__ void split2(float x, float y, uint32_t& hi, uint32_t& lo) {
    __half2 h, l;
    h.x = __float2half_rn(x);
    h.y = __float2half_rn(y);
    l.x = __float2half_rn(x - __half2float(h.x));
    l.y = __float2half_rn(y - __half2float(h.y));
    hi = *(uint32_t*)&h;
    lo = *(uint32_t*)&l;
}

// x half-buffer offset: row r (0..127), float4-slot f4 (0..31)
__device__ __forceinline__ uint32_t xo(int buf, int r, int f4) {
    return (uint32_t)XBUF(buf) + (uint32_t)r * 512u
         + ((((uint32_t)f4) ^ (((uint32_t)r & 3u) << 2)) << 4);
}
// h offset: row r, col c (fp32)
__device__ __forceinline__ uint32_t ho(int r, int c) {
    return (uint32_t)SM_HB + (uint32_t)r * 512u
         + (((((uint32_t)c >> 2)) ^ (((uint32_t)r & 3u) << 2)) << 4)
         + ((uint32_t)c & 3u) * 4u;
}

__global__ void __launch_bounds__(512, 1)
fused_gemm_seg_kernel(const float* __restrict__ x, const float* __restrict__ W,
                      const float* __restrict__ bvec, const int* __restrict__ seg)
{
    extern __shared__ char sm[];
    const uint32_t sb = smem_u32(sm);
    const int tid  = threadIdx.x;
    const int lane = tid & 31;
    const int wid  = tid >> 5;

    int*   seg_s = (int*)(sm + SM_SEG);
    float* b_s   = (float*)(sm + SM_B);

    // ---- one-time: W -> fp16, K-permuted within each 16-group, swizzled ----
    // permutation: actual k (s=k>>4, tq=(k&15)>>2, j=k&3) stored at mma k-pos
    // p = j<2 ? 2tq+j : 8+2tq+(j-2), so one float4 of x feeds (a0,a2) directly.
    for (int idx = tid; idx < BAG_K * FEAT_K; idx += 512) {
        int n = idx >> 8, k = idx & 255;
        int s = k >> 4, r = k & 15, tq = r >> 2, j = r & 3;
        int p = (j < 2) ? (2 * tq + j) : (8 + 2 * tq + (j - 2));
        int ks = 16 * s + p;
        uint32_t off = (uint32_t)n * 512u
                     + ((uint32_t)((ks >> 3) ^ (n & 7)) << 4)
                     + (uint32_t)(ks & 7) * 2u;
        *(__half*)(sm + SM_W + off) = __float2half_rn(W[idx]);
    }
    if (tid < BAG_K) b_s[tid] = bvec[tid];

    // warp tiling: 8 M-groups (16 rows) x 2 N-halves (64 cols)
    const int mgrp = wid >> 1;
    const int nq   = wid & 1;

    // fragment lane geometry
    const int g  = lane >> 2;
    const int tq = lane & 3;
    const int b_ln = ((lane >> 4) << 3) + (lane & 7);
    const int b_ku = (lane >> 3) & 1;
    const uint32_t b_base = (uint32_t)(nq * 64 + b_ln) * 512u;
    const uint32_t lane7  = (uint32_t)(lane & 7);
    const int R = mgrp * 16 + g;

    const float4* xf4 = (const float4*)x;

    // cp.async of one K-half of a tile
    auto issue_half = [&](int t, int kh, int buf) {
        const int i0 = t * TILE_K;
        #pragma unroll
        for (int it = 0; it < 8; it++) {
            int gg = it * 512 + tid;               // 4096 float4 slots
            int row = gg >> 5, f4 = gg & 31;
            cp_async16z(sb + xo(buf, row, f4),
                        xf4 + (size_t)(i0 + row) * 64 + kh * 32 + f4,
                        i0 + row < N_ITEMS_K);
        }
    };

    __syncthreads();   // W/b ready (before any compute uses them)

    // ---- prologue ----
    issue_half(blockIdx.x, 0, 0); CP_COMMIT();
    issue_half(blockIdx.x, 1, 1); CP_COMMIT();

    for (int t = blockIdx.x; t < N_TILES_K; t += gridDim.x) {
        const int i0 = t * TILE_K;
        const int rows = min(TILE_K, N_ITEMS_K - i0);
        const int tn = t + gridDim.x;
        int segreg = 0;
        if (tid < rows) segreg = seg[i0 + tid];

        float acc[8][4];
        #pragma unroll
        for (int n = 0; n < 8; n++)
            #pragma unroll
            for (int i = 0; i < 4; i++) acc[n][i] = 0.f;

        #pragma unroll 1
        for (int kh = 0; kh < 2; kh++) {
            CP_WAIT1();
            __syncthreads();
            const int buf = kh;

            #pragma unroll
            for (int s = 0; s < 8; s++) {
                // B fragments: this warp's 64 cols for global k-step kh*8+s
                const int sg = kh * 8 + s;
                const uint32_t bun = ((uint32_t)(2 * sg + b_ku) ^ lane7) << 4;
                uint32_t B[4][4];
                #pragma unroll
                for (int jj = 0; jj < 4; jj++)
                    ldsm4(B[jj], sb + SM_W + b_base + (uint32_t)jj * 8192u + bun);

                // A: one float4 per row covers (a0,a2) thanks to W permutation
                float4 v0 = *(const float4*)(sm + xo(buf, R,     4 * s + tq));
                float4 v1 = *(const float4*)(sm + xo(buf, R + 8, 4 * s + tq));
                uint32_t Ah[4], Al[4];
                split2(v0.x, v0.y, Ah[0], Al[0]);
                split2(v1.x, v1.y, Ah[1], Al[1]);
                split2(v0.z, v0.w, Ah[2], Al[2]);
                split2(v1.z, v1.w, Ah[3], Al[3]);

                #pragma unroll
                for (int n = 0; n < 4; n++) {
                    mma16816(acc[2*n],   Ah, B[n][0], B[n][1]);
                    mma16816(acc[2*n+1], Ah, B[n][2], B[n][3]);
                }
                #pragma unroll
                for (int n = 0; n < 4; n++) {
                    mma16816(acc[2*n],   Al, B[n][0], B[n][1]);
                    mma16816(acc[2*n+1], Al, B[n][2], B[n][3]);
                }
            }
            __syncthreads();   // all reads of this buffer done

            if (kh == 0) {     // refill buf0 with next tile's first half
                if (tn < N_TILES_K) issue_half(tn, 0, 0);
                CP_COMMIT();
            }
        }

        // ---- epilogue: +b, relu, h into buf1 region ----
        {
            const int c0 = nq * 64 + 2 * tq;
            #pragma unroll
            for (int n = 0; n < 8; n++) {
                const int c = c0 + n * 8;
                const float b0 = b_s[c], b1 = b_s[c + 1];
                float2 u0, u1;
                u0.x = fmaxf(acc[n][0] + b0, 0.f);
                u0.y = fmaxf(acc[n][1] + b1, 0.f);
                u1.x = fmaxf(acc[n][2] + b0, 0.f);
                u1.y = fmaxf(acc[n][3] + b1, 0.f);
                *(float2*)(sm + ho(R,     c)) = u0;
                *(float2*)(sm + ho(R + 8, c)) = u1;
            }
        }
        if (tid < rows) seg_s[tid] = segreg;
        __syncthreads();

        // ---- segment reduce: 4 row-groups x 128 columns ----
        {
            const int c    = tid & 127;
            const int r0   = (tid >> 7) * 32;
            const int rend = min(rows, r0 + 32);
            if (r0 < rows) {
                float a = 0.f;
                int cur = seg_s[r0];
                for (int r = r0; r < rend; r++) {
                    int s = seg_s[r];
                    if (s != cur) {
                        atomicAdd(&g_scratch[(size_t)cur * BAG_K + c], a);
                        a = 0.f;
                        cur = s;
                    }
                    a += *(const float*)(sm + ho(r, c));
                }
                atomicAdd(&g_scratch[(size_t)cur * BAG_K + c], a);
            }
        }
        __syncthreads();   // h reads done before buf1 refill

        if (tn < N_TILES_K) issue_half(tn, 1, 1);
        CP_COMMIT();
    }
}

// ---- per-column batch stats over the 50k bag means ----
__global__ void __launch_bounds__(128) stats_kernel(const int* __restrict__ blen)
{
    const int c = threadIdx.x;
    float s = 0.f, ss = 0.f;
    for (int r = blockIdx.x; r < N_BAGS_K; r += gridDim.x) {
        float cnt = (float)max(blen[r], 1);
        float v = g_scratch[(size_t)r * BAG_K + c] / cnt;
        s += v;
        ss += v * v;
    }
    atomicAdd(&g_scratch[(size_t)N_BAGS_K * BAG_K + c], s);
    atomicAdd(&g_scratch[(size_t)N_BAGS_K * BAG_K + BAG_K + c], ss);
}

// ---- normalize ----
__global__ void __launch_bounds__(128) norm_kernel(const int* __restrict__ blen,
                                                   const float* __restrict__ gamma,
                                                   const float* __restrict__ beta,
                                                   float* __restrict__ out)
{
    const int c = threadIdx.x;
    const float inv_n = 1.f / (float)N_BAGS_K;
    float mean = g_scratch[(size_t)N_BAGS_K * BAG_K + c] * inv_n;
    float ex2  = g_scratch[(size_t)N_BAGS_K * BAG_K + BAG_K + c] * inv_n;
    float scale = rsqrtf(ex2 - mean * mean + EPS_K) * gamma[c];
    float shift = beta[c];
    for (int r = blockIdx.x; r < N_BAGS_K; r += gridDim.x) {
        float cnt = (float)max(blen[r], 1);
        float v = g_scratch[(size_t)r * BAG_K + c] / cnt;
        out[(size_t)r * BAG_K + c] = (v - mean) * scale + shift;
    }
}

extern "C" void kernel_launch(void* const* d_in, const int* in_sizes, int n_in,
                              void* d_out, int out_size)
{
    const float* x     = (const float*)d_in[0];
    const float* W     = (const float*)d_in[1];
    const float* bvec  = (const float*)d_in[2];
    const float* gamma = (const float*)d_in[3];
    const float* beta  = (const float*)d_in[4];
    const int*   seg   = (const int*)d_in[5];
    const int*   blen  = (const int*)d_in[6];
    float*       out   = (float*)d_out;

    (void)in_sizes; (void)n_in; (void)out_size;

    void* scratch = nullptr;
    cudaGetSymbolAddress(&scratch, g_scratch);
    cudaMemsetAsync(scratch, 0,
                    sizeof(float) * ((size_t)N_BAGS_K * BAG_K + 2 * BAG_K), 0);

    int dev = 0, nsm = 148;
    cudaGetDevice(&dev);
    cudaDeviceGetAttribute(&nsm, cudaDevAttrMultiProcessorCount, dev);

    cudaFuncSetAttribute(fused_gemm_seg_kernel,
                         cudaFuncAttributeMaxDynamicSharedMemorySize, SMEM_DYN);
    fused_gemm_seg_kernel<<<nsm, 512, SMEM_DYN>>>(x, W, bvec, seg);
    stats_kernel<<<1024, 128>>>(blen);
    norm_kernel<<<2048, 128>>>(blen, gamma, beta, out);
}

// round 9
// speedup vs baseline: 1.4486x; 1.1819x over previous
#include <cuda_runtime.h>
#include <cuda_fp16.h>
#include <cstdint>

#define N_ITEMS_K 1000000
#define FEAT_K    256
#define BAG_K     128
#define N_BAGS_K  50000
#define TILE_K    128
#define N_TILES_K ((N_ITEMS_K + TILE_K - 1) / TILE_K)   // 7813 (last tile 64 rows)
#define EPS_K     1e-5f

// ---------------- device scratch ----------------
// [0, N_BAGS*BAG)       : segment sums
// [N_BAGS*BAG, +BAG)    : column sum of bag means
// [N_BAGS*BAG+BAG,+BAG) : column sum of squares
__device__ float g_scratch[(size_t)N_BAGS_K * BAG_K + 2 * BAG_K];

// ---------------- shared memory layout (byte offsets) ----------------
// seg ids : [0, 512)
// b vec   : [512, 1024)
// W fp16  : [1024, 66560)     128 rows x 512 B, K-permuted + XOR swizzle
// buf0    : [66560, 132096)   128 rows x 512 B fp32 (K-half), XOR swizzle
// buf1    : [132096, 197632)  (h fp32 128x512B aliases buf1 in epilogue)
#define SM_SEG   0
#define SM_B     512
#define SM_W     1024
#define XBUF(b)  (66560 + (b) * 65536)
#define SM_HB    132096
#define SMEM_DYN 197632

__device__ __forceinline__ uint32_t smem_u32(const void* p) {
    uint32_t a;
    asm("{ .reg .u64 t; cvta.to.shared.u64 t, %1; cvt.u32.u64 %0, t; }" : "=r"(a) : "l"(p));
    return a;
}

__device__ __forceinline__ void ldsm4(uint32_t* r, uint32_t addr) {
    asm volatile("ldmatrix.sync.aligned.m8n8.x4.shared.b16 {%0,%1,%2,%3}, [%4];"
                 : "=r"(r[0]), "=r"(r[1]), "=r"(r[2]), "=r"(r[3]) : "r"(addr));
}

__device__ __forceinline__ void mma16816(float* c, const uint32_t* a,
                                         uint32_t b0, uint32_t b1) {
    asm volatile(
        "mma.sync.aligned.m16n8k16.row.col.f32.f16.f16.f32 "
        "{%0,%1,%2,%3},{%4,%5,%6,%7},{%8,%9},{%0,%1,%2,%3};"
        : "+f"(c[0]), "+f"(c[1]), "+f"(c[2]), "+f"(c[3])
        : "r"(a[0]), "r"(a[1]), "r"(a[2]), "r"(a[3]), "r"(b0), "r"(b1));
}

__device__ __forceinline__ void cp_async16z(uint32_t dst, const void* src, bool pred) {
    int sz = pred ? 16 : 0;
    asm volatile("cp.async.cg.shared.global [%0], [%1], 16, %2;"
                 :: "r"(dst), "l"(src), "r"(sz) : "memory");
}
#define CP_COMMIT() asm volatile("cp.async.commit_group;" ::: "memory")
#define CP_WAIT1()  asm volatile("cp.async.wait_group 1;" ::: "memory")

// x half-buffer offset: row r (0..127), float4-slot f4 (0..31)
__device__ __forceinline__ uint32_t xo(int buf, int r, int f4) {
    return (uint32_t)XBUF(buf) + (uint32_t)r * 512u
         + ((((uint32_t)f4) ^ (((uint32_t)r & 3u) << 2)) << 4);
}
// h offset: row r, col c (fp32)
__device__ __forceinline__ uint32_t ho(int r, int c) {
    return (uint32_t)SM_HB + (uint32_t)r * 512u
         + (((((uint32_t)c >> 2)) ^ (((uint32_t)r & 3u) << 2)) << 4)
         + ((uint32_t)c & 3u) * 4u;
}

__global__ void __launch_bounds__(512, 1)
fused_gemm_seg_kernel(const float* __restrict__ x, const float* __restrict__ W,
                      const float* __restrict__ bvec, const int* __restrict__ seg)
{
    extern __shared__ char sm[];
    const uint32_t sb = smem_u32(sm);
    const int tid  = threadIdx.x;
    const int lane = tid & 31;
    const int wid  = tid >> 5;

    int*   seg_s = (int*)(sm + SM_SEG);
    float* b_s   = (float*)(sm + SM_B);

    // ---- one-time: W -> fp16, K-permuted within each 16-group, swizzled ----
    for (int idx = tid; idx < BAG_K * FEAT_K; idx += 512) {
        int n = idx >> 8, k = idx & 255;
        int s = k >> 4, r = k & 15, tq = r >> 2, j = r & 3;
        int p = (j < 2) ? (2 * tq + j) : (8 + 2 * tq + (j - 2));
        int ks = 16 * s + p;
        uint32_t off = (uint32_t)n * 512u
                     + ((uint32_t)((ks >> 3) ^ (n & 7)) << 4)
                     + (uint32_t)(ks & 7) * 2u;
        *(__half*)(sm + SM_W + off) = __float2half_rn(W[idx]);
    }
    if (tid < BAG_K) b_s[tid] = bvec[tid];

    // warp tiling: 8 M-groups (16 rows) x 2 N-halves (64 cols)
    const int mgrp = wid >> 1;
    const int nq   = wid & 1;

    // fragment lane geometry
    const int g  = lane >> 2;
    const int tq = lane & 3;
    const int b_ln = ((lane >> 4) << 3) + (lane & 7);
    const int b_ku = (lane >> 3) & 1;
    const uint32_t b_base = (uint32_t)(nq * 64 + b_ln) * 512u;
    const uint32_t lane7  = (uint32_t)(lane & 7);
    const int R = mgrp * 16 + g;

    const float4* xf4 = (const float4*)x;

    auto issue_half = [&](int t, int kh, int buf) {
        const int i0 = t * TILE_K;
        #pragma unroll
        for (int it = 0; it < 8; it++) {
            int gg = it * 512 + tid;               // 4096 float4 slots
            int row = gg >> 5, f4 = gg & 31;
            cp_async16z(sb + xo(buf, row, f4),
                        xf4 + (size_t)(i0 + row) * 64 + kh * 32 + f4,
                        i0 + row < N_ITEMS_K);
        }
    };

    __syncthreads();   // W/b ready

    // ---- prologue ----
    issue_half(blockIdx.x, 0, 0); CP_COMMIT();
    issue_half(blockIdx.x, 1, 1); CP_COMMIT();

    for (int t = blockIdx.x; t < N_TILES_K; t += gridDim.x) {
        const int i0 = t * TILE_K;
        const int rows = min(TILE_K, N_ITEMS_K - i0);
        const int tn = t + gridDim.x;
        int segreg = 0;
        if (tid < rows) segreg = seg[i0 + tid];

        float acc[8][4];
        #pragma unroll
        for (int n = 0; n < 8; n++)
            #pragma unroll
            for (int i = 0; i < 4; i++) acc[n][i] = 0.f;

        #pragma unroll 1
        for (int kh = 0; kh < 2; kh++) {
            CP_WAIT1();
            __syncthreads();
            const int buf = kh;

            #pragma unroll
            for (int s = 0; s < 8; s++) {
                const int sg = kh * 8 + s;
                const uint32_t bun = ((uint32_t)(2 * sg + b_ku) ^ lane7) << 4;
                uint32_t B[4][4];
                #pragma unroll
                for (int jj = 0; jj < 4; jj++)
                    ldsm4(B[jj], sb + SM_W + b_base + (uint32_t)jj * 8192u + bun);

                // A: one float4 per row covers (a0,a2); hi-fp16 only
                float4 v0 = *(const float4*)(sm + xo(buf, R,     4 * s + tq));
                float4 v1 = *(const float4*)(sm + xo(buf, R + 8, 4 * s + tq));
                uint32_t Ah[4];
                __half2 h0 = __float22half2_rn(make_float2(v0.x, v0.y));
                __half2 h1 = __float22half2_rn(make_float2(v1.x, v1.y));
                __half2 h2 = __float22half2_rn(make_float2(v0.z, v0.w));
                __half2 h3 = __float22half2_rn(make_float2(v1.z, v1.w));
                Ah[0] = *(uint32_t*)&h0;
                Ah[1] = *(uint32_t*)&h1;
                Ah[2] = *(uint32_t*)&h2;
                Ah[3] = *(uint32_t*)&h3;

                #pragma unroll
                for (int n = 0; n < 4; n++) {
                    mma16816(acc[2*n],   Ah, B[n][0], B[n][1]);
                    mma16816(acc[2*n+1], Ah, B[n][2], B[n][3]);
                }
            }
            __syncthreads();

            if (kh == 0) {
                if (tn < N_TILES_K) issue_half(tn, 0, 0);
                CP_COMMIT();
            }
        }

        // ---- epilogue: +b, relu, h into buf1 region ----
        {
            const int c0 = nq * 64 + 2 * tq;
            #pragma unroll
            for (int n = 0; n < 8; n++) {
                const int c = c0 + n * 8;
                const float b0 = b_s[c], b1 = b_s[c + 1];
                float2 u0, u1;
                u0.x = fmaxf(acc[n][0] + b0, 0.f);
                u0.y = fmaxf(acc[n][1] + b1, 0.f);
                u1.x = fmaxf(acc[n][2] + b0, 0.f);
                u1.y = fmaxf(acc[n][3] + b1, 0.f);
                *(float2*)(sm + ho(R,     c)) = u0;
                *(float2*)(sm + ho(R + 8, c)) = u1;
            }
        }
        if (tid < rows) seg_s[tid] = segreg;
        __syncthreads();

        // ---- segment reduce: 4 row-groups x 128 columns ----
        {
            const int c    = tid & 127;
            const int r0   = (tid >> 7) * 32;
            const int rend = min(rows, r0 + 32);
            if (r0 < rows) {
                float a = 0.f;
                int cur = seg_s[r0];
                for (int r = r0; r < rend; r++) {
                    int s = seg_s[r];
                    if (s != cur) {
                        atomicAdd(&g_scratch[(size_t)cur * BAG_K + c], a);
                        a = 0.f;
                        cur = s;
                    }
                    a += *(const float*)(sm + ho(r, c));
                }
                atomicAdd(&g_scratch[(size_t)cur * BAG_K + c], a);
            }
        }
        __syncthreads();   // h reads done before buf1 refill

        if (tn < N_TILES_K) issue_half(tn, 1, 1);
        CP_COMMIT();
    }
}

// ---- per-column batch stats over the 50k bag means (vectorized) ----
__global__ void __launch_bounds__(256) stats_kernel(const int* __restrict__ blen)
{
    __shared__ float4 red_s[8][32];
    __shared__ float4 red_ss[8][32];
    const int c4 = threadIdx.x & 31;     // float4 column group (128 cols / 4)
    const int rs = threadIdx.x >> 5;     // 0..7 row sub-lane
    float4 s  = make_float4(0.f, 0.f, 0.f, 0.f);
    float4 ss = make_float4(0.f, 0.f, 0.f, 0.f);
    const float4* gs = (const float4*)g_scratch;
    for (int r = blockIdx.x * 8 + rs; r < N_BAGS_K; r += gridDim.x * 8) {
        float inv = 1.f / (float)max(blen[r], 1);
        float4 v = gs[(size_t)r * 32 + c4];
        v.x *= inv; v.y *= inv; v.z *= inv; v.w *= inv;
        s.x += v.x;  s.y += v.y;  s.z += v.z;  s.w += v.w;
        ss.x += v.x * v.x; ss.y += v.y * v.y; ss.z += v.z * v.z; ss.w += v.w * v.w;
    }
    red_s[rs][c4]  = s;
    red_ss[rs][c4] = ss;
    __syncthreads();
    if (rs == 0) {
        #pragma unroll
        for (int i = 1; i < 8; i++) {
            float4 a = red_s[i][c4], b = red_ss[i][c4];
            s.x += a.x; s.y += a.y; s.z += a.z; s.w += a.w;
            ss.x += b.x; ss.y += b.y; ss.z += b.z; ss.w += b.w;
        }
        float* dst  = &g_scratch[(size_t)N_BAGS_K * BAG_K + c4 * 4];
        float* dst2 = &g_scratch[(size_t)N_BAGS_K * BAG_K + BAG_K + c4 * 4];
        atomicAdd(dst + 0, s.x);  atomicAdd(dst + 1, s.y);
        atomicAdd(dst + 2, s.z);  atomicAdd(dst + 3, s.w);
        atomicAdd(dst2 + 0, ss.x); atomicAdd(dst2 + 1, ss.y);
        atomicAdd(dst2 + 2, ss.z); atomicAdd(dst2 + 3, ss.w);
    }
}

// ---- normalize (vectorized) ----
__global__ void __launch_bounds__(256) norm_kernel(const int* __restrict__ blen,
                                                   const float* __restrict__ gamma,
                                                   const float* __restrict__ beta,
                                                   float* __restrict__ out)
{
    const int c4 = threadIdx.x & 31;
    const int rs = threadIdx.x >> 5;
    const float inv_n = 1.f / (float)N_BAGS_K;
    float4 m = *(const float4*)&g_scratch[(size_t)N_BAGS_K * BAG_K + c4 * 4];
    float4 e = *(const float4*)&g_scratch[(size_t)N_BAGS_K * BAG_K + BAG_K + c4 * 4];
    float4 ga = ((const float4*)gamma)[c4];
    float4 be = ((const float4*)beta)[c4];
    float4 mean, scale;
    mean.x = m.x * inv_n; mean.y = m.y * inv_n;
    mean.z = m.z * inv_n; mean.w = m.w * inv_n;
    scale.x = rsqrtf(e.x * inv_n - mean.x * mean.x + EPS_K) * ga.x;
    scale.y = rsqrtf(e.y * inv_n - mean.y * mean.y + EPS_K) * ga.y;
    scale.z = rsqrtf(e.z * inv_n - mean.z * mean.z + EPS_K) * ga.z;
    scale.w = rsqrtf(e.w * inv_n - mean.w * mean.w + EPS_K) * ga.w;
    const float4* gs = (const float4*)g_scratch;
    float4* o4 = (float4*)out;
    for (int r = blockIdx.x * 8 + rs; r < N_BAGS_K; r += gridDim.x * 8) {
        float inv = 1.f / (float)max(blen[r], 1);
        float4 v = gs[(size_t)r * 32 + c4];
        float4 o;
        o.x = (v.x * inv - mean.x) * scale.x + be.x;
        o.y = (v.y * inv - mean.y) * scale.y + be.y;
        o.z = (v.z * inv - mean.z) * scale.z + be.z;
        o.w = (v.w * inv - mean.w) * scale.w + be.w;
        o4[(size_t)r * 32 + c4] = o;
    }
}

extern "C" void kernel_launch(void* const* d_in, const int* in_sizes, int n_in,
                              void* d_out, int out_size)
{
    const float* x     = (const float*)d_in[0];
    const float* W     = (const float*)d_in[1];
    const float* bvec  = (const float*)d_in[2];
    const float* gamma = (const float*)d_in[3];
    const float* beta  = (const float*)d_in[4];
    const int*   seg   = (const int*)d_in[5];
    const int*   blen  = (const int*)d_in[6];
    float*       out   = (float*)d_out;

    (void)in_sizes; (void)n_in; (void)out_size;

    void* scratch = nullptr;
    cudaGetSymbolAddress(&scratch, g_scratch);
    cudaMemsetAsync(scratch, 0,
                    sizeof(float) * ((size_t)N_BAGS_K * BAG_K + 2 * BAG_K), 0);

    int dev = 0, nsm = 148;
    cudaGetDevice(&dev);
    cudaDeviceGetAttribute(&nsm, cudaDevAttrMultiProcessorCount, dev);

    cudaFuncSetAttribute(fused_gemm_seg_kernel,
                         cudaFuncAttributeMaxDynamicSharedMemorySize, SMEM_DYN);
    fused_gemm_seg_kernel<<<nsm, 512, SMEM_DYN>>>(x, W, bvec, seg);
    stats_kernel<<<128, 256>>>(blen);
    norm_kernel<<<512, 256>>>(blen, gamma, beta, out);
}

// round 10
// speedup vs baseline: 1.6434x; 1.1345x over previous
#include <cuda_runtime.h>
#include <cuda_fp16.h>
#include <cstdint>

#define N_ITEMS_K 1000000
#define FEAT_K    256
#define BAG_K     128
#define N_BAGS_K  50000
#define TILE_K    256
#define N_TILES_K ((N_ITEMS_K + TILE_K - 1) / TILE_K)   // 3907 (last tile 64 rows)
#define EPS_K     1e-5f

// ---------------- device scratch ----------------
// [0, N_BAGS*BAG)       : segment sums
// [N_BAGS*BAG, +BAG)    : column sum of bag means
// [N_BAGS*BAG+BAG,+BAG) : column sum of squares
__device__ float g_scratch[(size_t)N_BAGS_K * BAG_K + 2 * BAG_K];

// ---------------- shared memory layout (byte offsets) ----------------
// seg ids : [0, 1024)        256 ints
// b vec   : [1024, 1536)
// W fp16  : [2048, 67584)    128 rows x 512 B, K-permuted + XOR swizzle
// xq0     : [67584, 133120)  256 rows x 256 B fp32 (K-quarter), swizzled
// xq1     : [133120, 198656)
// h       : aliases [67584, 198656)  256 rows x 512 B fp32
#define SM_SEG   0
#define SM_B     1024
#define SM_W     2048
#define XQ(b)    (67584 + (b) * 65536)
#define SM_HB    67584
#define SMEM_DYN 198656

__device__ __forceinline__ uint32_t smem_u32(const void* p) {
    uint32_t a;
    asm("{ .reg .u64 t; cvta.to.shared.u64 t, %1; cvt.u32.u64 %0, t; }" : "=r"(a) : "l"(p));
    return a;
}

__device__ __forceinline__ void ldsm4(uint32_t* r, uint32_t addr) {
    asm volatile("ldmatrix.sync.aligned.m8n8.x4.shared.b16 {%0,%1,%2,%3}, [%4];"
                 : "=r"(r[0]), "=r"(r[1]), "=r"(r[2]), "=r"(r[3]) : "r"(addr));
}

__device__ __forceinline__ void mma16816(float* c, const uint32_t* a,
                                         uint32_t b0, uint32_t b1) {
    asm volatile(
        "mma.sync.aligned.m16n8k16.row.col.f32.f16.f16.f32 "
        "{%0,%1,%2,%3},{%4,%5,%6,%7},{%8,%9},{%0,%1,%2,%3};"
        : "+f"(c[0]), "+f"(c[1]), "+f"(c[2]), "+f"(c[3])
        : "r"(a[0]), "r"(a[1]), "r"(a[2]), "r"(a[3]), "r"(b0), "r"(b1));
}

__device__ __forceinline__ void cp_async16z(uint32_t dst, const void* src, bool pred) {
    int sz = pred ? 16 : 0;
    asm volatile("cp.async.cg.shared.global [%0], [%1], 16, %2;"
                 :: "r"(dst), "l"(src), "r"(sz) : "memory");
}
#define CP_COMMIT() asm volatile("cp.async.commit_group;" ::: "memory")
#define CP_WAIT1()  asm volatile("cp.async.wait_group 1;" ::: "memory")
#define CP_WAIT0()  asm volatile("cp.async.wait_group 0;" ::: "memory")

// x quarter-buffer offset: row r (0..255), float4-slot f4 (0..15)
__device__ __forceinline__ uint32_t xo(int buf, int r, int f4) {
    return (uint32_t)XQ(buf) + (uint32_t)r * 256u
         + ((((uint32_t)f4) ^ (((uint32_t)r & 1u) << 2)) << 4);
}
// h offset: row r (0..255), col c (fp32, 0..127)
__device__ __forceinline__ uint32_t ho(int r, int c) {
    return (uint32_t)SM_HB + (uint32_t)r * 512u
         + (((((uint32_t)c >> 2)) ^ (((uint32_t)r & 7u) << 1)) << 4)
         + ((uint32_t)c & 3u) * 4u;
}

__global__ void __launch_bounds__(512, 1)
fused_gemm_seg_kernel(const float* __restrict__ x, const float* __restrict__ W,
                      const float* __restrict__ bvec, const int* __restrict__ seg)
{
    extern __shared__ char sm[];
    const uint32_t sb = smem_u32(sm);
    const int tid  = threadIdx.x;
    const int lane = tid & 31;
    const int wid  = tid >> 5;

    int*   seg_s = (int*)(sm + SM_SEG);
    float* b_s   = (float*)(sm + SM_B);

    // ---- one-time: W -> fp16, K-permuted within each 16-group, swizzled ----
    for (int idx = tid; idx < BAG_K * FEAT_K; idx += 512) {
        int n = idx >> 8, k = idx & 255;
        int s = k >> 4, r = k & 15, tq = r >> 2, j = r & 3;
        int p = (j < 2) ? (2 * tq + j) : (8 + 2 * tq + (j - 2));
        int ks = 16 * s + p;
        uint32_t off = (uint32_t)n * 512u
                     + ((uint32_t)((ks >> 3) ^ (n & 7)) << 4)
                     + (uint32_t)(ks & 7) * 2u;
        *(__half*)(sm + SM_W + off) = __float2half_rn(W[idx]);
    }
    if (tid < BAG_K) b_s[tid] = bvec[tid];

    // warp tiling: 8 M-groups (32 rows each) x 2 N-halves (64 cols)
    const int mgrp = wid >> 1;
    const int nq   = wid & 1;

    // fragment lane geometry
    const int g  = lane >> 2;
    const int tq = lane & 3;
    const int b_ln = ((lane >> 4) << 3) + (lane & 7);
    const int b_ku = (lane >> 3) & 1;
    const uint32_t b_base = (uint32_t)(nq * 64 + b_ln) * 512u;
    const uint32_t lane7  = (uint32_t)(lane & 7);
    const int R = mgrp * 32 + g;          // fragment rows R,R+8 (m=0), R+16,R+24 (m=1)

    const float4* xf4 = (const float4*)x;

    // cp.async of one K-quarter (64 feats) of a 256-row tile
    auto issue_q = [&](int t, int q, int buf) {
        const int i0 = t * TILE_K;
        #pragma unroll
        for (int it = 0; it < 8; it++) {
            int gg = it * 512 + tid;               // 4096 float4 slots
            int row = gg >> 4, f4 = gg & 15;
            cp_async16z(sb + xo(buf, row, f4),
                        xf4 + (size_t)(i0 + row) * 64 + q * 16 + f4,
                        i0 + row < N_ITEMS_K);
        }
    };

    __syncthreads();   // W/b ready

    // ---- prologue: quarters 0,1 of first tile ----
    issue_q(blockIdx.x, 0, 0); CP_COMMIT();
    issue_q(blockIdx.x, 1, 1); CP_COMMIT();

    for (int t = blockIdx.x; t < N_TILES_K; t += gridDim.x) {
        const int i0 = t * TILE_K;
        const int rows = min(TILE_K, N_ITEMS_K - i0);
        const int tn = t + gridDim.x;
        const int tnc = (tn < N_TILES_K) ? tn : t;   // clamp: redundant, never consumed
        int segreg = 0;
        if (tid < rows) segreg = seg[i0 + tid];

        float acc[2][8][4];
        #pragma unroll
        for (int m = 0; m < 2; m++)
            #pragma unroll
            for (int n = 0; n < 8; n++)
                #pragma unroll
                for (int i = 0; i < 4; i++) acc[m][n][i] = 0.f;

        #pragma unroll 1
        for (int q = 0; q < 4; q++) {
            if (q < 3) { CP_WAIT1(); } else { CP_WAIT0(); }
            __syncthreads();
            const int buf = q & 1;

            #pragma unroll
            for (int s = 0; s < 4; s++) {
                const int sg = q * 4 + s;
                const uint32_t bun = ((uint32_t)(2 * sg + b_ku) ^ lane7) << 4;
                uint32_t B[4][4];
                #pragma unroll
                for (int jj = 0; jj < 4; jj++)
                    ldsm4(B[jj], sb + SM_W + b_base + (uint32_t)jj * 8192u + bun);

                const int f4 = 4 * s + tq;
                #pragma unroll
                for (int m = 0; m < 2; m++) {
                    const int Rm = R + 16 * m;
                    float4 v0 = *(const float4*)(sm + xo(buf, Rm,     f4));
                    float4 v1 = *(const float4*)(sm + xo(buf, Rm + 8, f4));
                    uint32_t Ah[4];
                    __half2 h0 = __float22half2_rn(make_float2(v0.x, v0.y));
                    __half2 h1 = __float22half2_rn(make_float2(v1.x, v1.y));
                    __half2 h2 = __float22half2_rn(make_float2(v0.z, v0.w));
                    __half2 h3 = __float22half2_rn(make_float2(v1.z, v1.w));
                    Ah[0] = *(uint32_t*)&h0;
                    Ah[1] = *(uint32_t*)&h1;
                    Ah[2] = *(uint32_t*)&h2;
                    Ah[3] = *(uint32_t*)&h3;

                    #pragma unroll
                    for (int n = 0; n < 4; n++) {
                        mma16816(acc[m][2*n],   Ah, B[n][0], B[n][1]);
                        mma16816(acc[m][2*n+1], Ah, B[n][2], B[n][3]);
                    }
                }
            }
            __syncthreads();   // all reads of this buffer done

            if (q == 0)      { issue_q(tnc == t ? t : t, q + 2, buf); CP_COMMIT(); }
            else if (q == 1) { issue_q(t, q + 2, buf); CP_COMMIT(); }
            // note: q2/q3 of CURRENT tile t (quarters 2,3), issued into freed bufs
        }

        // ---- epilogue: +b, relu, h over both buffer regions ----
        {
            const int c0 = nq * 64 + 2 * tq;
            #pragma unroll
            for (int m = 0; m < 2; m++) {
                const int Rm = R + 16 * m;
                #pragma unroll
                for (int n = 0; n < 8; n++) {
                    const int c = c0 + n * 8;
                    const float b0 = b_s[c], b1 = b_s[c + 1];
                    float2 u0, u1;
                    u0.x = fmaxf(acc[m][n][0] + b0, 0.f);
                    u0.y = fmaxf(acc[m][n][1] + b1, 0.f);
                    u1.x = fmaxf(acc[m][n][2] + b0, 0.f);
                    u1.y = fmaxf(acc[m][n][3] + b1, 0.f);
                    *(float2*)(sm + ho(Rm,     c)) = u0;
                    *(float2*)(sm + ho(Rm + 8, c)) = u1;
                }
            }
        }
        if (tid < rows) seg_s[tid] = segreg;
        __syncthreads();

        // ---- segment reduce: 4 row-groups (64 rows) x 128 columns ----
        {
            const int c    = tid & 127;
            const int r0   = (tid >> 7) * 64;
            const int rend = min(rows, r0 + 64);
            if (r0 < rows) {
                float a = 0.f;
                int cur = seg_s[r0];
                for (int r = r0; r < rend; r++) {
                    int s = seg_s[r];
                    if (s != cur) {
                        atomicAdd(&g_scratch[(size_t)cur * BAG_K + c], a);
                        a = 0.f;
                        cur = s;
                    }
                    a += *(const float*)(sm + ho(r, c));
                }
                atomicAdd(&g_scratch[(size_t)cur * BAG_K + c], a);
            }
        }
        __syncthreads();   // h reads done before buffers are refilled

        // ---- prefetch next tile's quarters 0,1 (clamped if past end) ----
        issue_q(tnc, 0, 0); CP_COMMIT();
        issue_q(tnc, 1, 1); CP_COMMIT();
    }
}

// ---- per-column batch stats over the 50k bag means (vectorized) ----
__global__ void __launch_bounds__(256) stats_kernel(const int* __restrict__ blen)
{
    __shared__ float4 red_s[8][32];
    __shared__ float4 red_ss[8][32];
    const int c4 = threadIdx.x & 31;
    const int rs = threadIdx.x >> 5;
    float4 s  = make_float4(0.f, 0.f, 0.f, 0.f);
    float4 ss = make_float4(0.f, 0.f, 0.f, 0.f);
    const float4* gs = (const float4*)g_scratch;
    for (int r = blockIdx.x * 8 + rs; r < N_BAGS_K; r += gridDim.x * 8) {
        float inv = 1.f / (float)max(blen[r], 1);
        float4 v = gs[(size_t)r * 32 + c4];
        v.x *= inv; v.y *= inv; v.z *= inv; v.w *= inv;
        s.x += v.x;  s.y += v.y;  s.z += v.z;  s.w += v.w;
        ss.x += v.x * v.x; ss.y += v.y * v.y; ss.z += v.z * v.z; ss.w += v.w * v.w;
    }
    red_s[rs][c4]  = s;
    red_ss[rs][c4] = ss;
    __syncthreads();
    if (rs == 0) {
        #pragma unroll
        for (int i = 1; i < 8; i++) {
            float4 a = red_s[i][c4], b = red_ss[i][c4];
            s.x += a.x; s.y += a.y; s.z += a.z; s.w += a.w;
            ss.x += b.x; ss.y += b.y; ss.z += b.z; ss.w += b.w;
        }
        float* dst  = &g_scratch[(size_t)N_BAGS_K * BAG_K + c4 * 4];
        float* dst2 = &g_scratch[(size_t)N_BAGS_K * BAG_K + BAG_K + c4 * 4];
        atomicAdd(dst + 0, s.x);  atomicAdd(dst + 1, s.y);
        atomicAdd(dst + 2, s.z);  atomicAdd(dst + 3, s.w);
        atomicAdd(dst2 + 0, ss.x); atomicAdd(dst2 + 1, ss.y);
        atomicAdd(dst2 + 2, ss.z); atomicAdd(dst2 + 3, ss.w);
    }
}

// ---- normalize (vectorized) ----
__global__ void __launch_bounds__(256) norm_kernel(const int* __restrict__ blen,
                                                   const float* __restrict__ gamma,
                                                   const float* __restrict__ beta,
                                                   float* __restrict__ out)
{
    const int c4 = threadIdx.x & 31;
    const int rs = threadIdx.x >> 5;
    const float inv_n = 1.f / (float)N_BAGS_K;
    float4 m = *(const float4*)&g_scratch[(size_t)N_BAGS_K * BAG_K + c4 * 4];
    float4 e = *(const float4*)&g_scratch[(size_t)N_BAGS_K * BAG_K + BAG_K + c4 * 4];
    float4 ga = ((const float4*)gamma)[c4];
    float4 be = ((const float4*)beta)[c4];
    float4 mean, scale;
    mean.x = m.x * inv_n; mean.y = m.y * inv_n;
    mean.z = m.z * inv_n; mean.w = m.w * inv_n;
    scale.x = rsqrtf(e.x * inv_n - mean.x * mean.x + EPS_K) * ga.x;
    scale.y = rsqrtf(e.y * inv_n - mean.y * mean.y + EPS_K) * ga.y;
    scale.z = rsqrtf(e.z * inv_n - mean.z * mean.z + EPS_K) * ga.z;
    scale.w = rsqrtf(e.w * inv_n - mean.w * mean.w + EPS_K) * ga.w;
    const float4* gs = (const float4*)g_scratch;
    float4* o4 = (float4*)out;
    for (int r = blockIdx.x * 8 + rs; r < N_BAGS_K; r += gridDim.x * 8) {
        float inv = 1.f / (float)max(blen[r], 1);
        float4 v = gs[(size_t)r * 32 + c4];
        float4 o;
        o.x = (v.x * inv - mean.x) * scale.x + be.x;
        o.y = (v.y * inv - mean.y) * scale.y + be.y;
        o.z = (v.z * inv - mean.z) * scale.z + be.z;
        o.w = (v.w * inv - mean.w) * scale.w + be.w;
        o4[(size_t)r * 32 + c4] = o;
    }
}

extern "C" void kernel_launch(void* const* d_in, const int* in_sizes, int n_in,
                              void* d_out, int out_size)
{
    const float* x     = (const float*)d_in[0];
    const float* W     = (const float*)d_in[1];
    const float* bvec  = (const float*)d_in[2];
    const float* gamma = (const float*)d_in[3];
    const float* beta  = (const float*)d_in[4];
    const int*   seg   = (const int*)d_in[5];
    const int*   blen  = (const int*)d_in[6];
    float*       out   = (float*)d_out;

    (void)in_sizes; (void)n_in; (void)out_size;

    void* scratch = nullptr;
    cudaGetSymbolAddress(&scratch, g_scratch);
    cudaMemsetAsync(scratch, 0,
                    sizeof(float) * ((size_t)N_BAGS_K * BAG_K + 2 * BAG_K), 0);

    int dev = 0, nsm = 148;
    cudaGetDevice(&dev);
    cudaDeviceGetAttribute(&nsm, cudaDevAttrMultiProcessorCount, dev);

    cudaFuncSetAttribute(fused_gemm_seg_kernel,
                         cudaFuncAttributeMaxDynamicSharedMemorySize, SMEM_DYN);
    fused_gemm_seg_kernel<<<nsm, 512, SMEM_DYN>>>(x, W, bvec, seg);
    stats_kernel<<<256, 256>>>(blen);
    norm_kernel<<<1024, 256>>>(blen, gamma, beta, out);
}

// round 11
// speedup vs baseline: 1.7919x; 1.0904x over previous
#include <cuda_runtime.h>
#include <cuda_fp16.h>
#include <cstdint>

#define N_ITEMS_K 1000000
#define FEAT_K    256
#define BAG_K     128
#define N_BAGS_K  50000
#define TILE_K    256
#define N_TILES_K ((N_ITEMS_K + TILE_K - 1) / TILE_K)   // 3907 (last tile 64 rows)
#define EPS_K     1e-5f

// ---------------- device scratch ----------------
__device__ float g_scratch[(size_t)N_BAGS_K * BAG_K + 2 * BAG_K];

// ---------------- shared memory layout (byte offsets) ----------------
// seg ids : [0, 1024)
// b vec   : [1024, 1536)
// W fp16  : [2048, 67584)    128 rows x 512 B, K-permuted + XOR swizzle
// xq b0   : [67584, 133120)  256 rows x 256 B fp32 (K-quarter), swizzled
// xq b1   : [133120, 198656)
// h fp16  : aliases b1 [133120, 198656)  256 rows x 256 B
#define SM_SEG   0
#define SM_B     1024
#define SM_W     2048
#define XQ0      67584
#define SM_H16   133120
#define SMEM_DYN 198656

__device__ __forceinline__ uint32_t smem_u32(const void* p) {
    uint32_t a;
    asm("{ .reg .u64 t; cvta.to.shared.u64 t, %1; cvt.u32.u64 %0, t; }" : "=r"(a) : "l"(p));
    return a;
}

__device__ __forceinline__ void ldsm4(uint32_t* r, uint32_t addr) {
    asm volatile("ldmatrix.sync.aligned.m8n8.x4.shared.b16 {%0,%1,%2,%3}, [%4];"
                 : "=r"(r[0]), "=r"(r[1]), "=r"(r[2]), "=r"(r[3]) : "r"(addr));
}

__device__ __forceinline__ void mma16816(float* c, const uint32_t* a,
                                         uint32_t b0, uint32_t b1) {
    asm volatile(
        "mma.sync.aligned.m16n8k16.row.col.f32.f16.f16.f32 "
        "{%0,%1,%2,%3},{%4,%5,%6,%7},{%8,%9},{%0,%1,%2,%3};"
        : "+f"(c[0]), "+f"(c[1]), "+f"(c[2]), "+f"(c[3])
        : "r"(a[0]), "r"(a[1]), "r"(a[2]), "r"(a[3]), "r"(b0), "r"(b1));
}

__device__ __forceinline__ void cp_async16z(uint32_t dst, const void* src, bool pred) {
    int sz = pred ? 16 : 0;
    asm volatile("cp.async.cg.shared.global [%0], [%1], 16, %2;"
                 :: "r"(dst), "l"(src), "r"(sz) : "memory");
}
#define CP_COMMIT() asm volatile("cp.async.commit_group;" ::: "memory")
#define CP_WAIT1()  asm volatile("cp.async.wait_group 1;" ::: "memory")
#define CP_WAIT0()  asm volatile("cp.async.wait_group 0;" ::: "memory")

__global__ void __launch_bounds__(512, 1)
fused_gemm_seg_kernel(const float* __restrict__ x, const float* __restrict__ W,
                      const float* __restrict__ bvec, const int* __restrict__ seg)
{
    extern __shared__ char sm[];
    const uint32_t sb = smem_u32(sm);
    const int tid  = threadIdx.x;
    const int lane = tid & 31;
    const int wid  = tid >> 5;

    int*   seg_s = (int*)(sm + SM_SEG);
    float* b_s   = (float*)(sm + SM_B);

    // ---- one-time: W -> fp16, K-permuted within each 16-group, swizzled ----
    for (int idx = tid; idx < BAG_K * FEAT_K; idx += 512) {
        int n = idx >> 8, k = idx & 255;
        int s = k >> 4, r = k & 15, tq = r >> 2, j = r & 3;
        int p = (j < 2) ? (2 * tq + j) : (8 + 2 * tq + (j - 2));
        int ks = 16 * s + p;
        uint32_t off = (uint32_t)n * 512u
                     + ((uint32_t)((ks >> 3) ^ (n & 7)) << 4)
                     + (uint32_t)(ks & 7) * 2u;
        *(__half*)(sm + SM_W + off) = __float2half_rn(W[idx]);
    }
    if (tid < BAG_K) b_s[tid] = bvec[tid];

    // warp tiling: 8 M-groups (32 rows each) x 2 N-halves (64 cols)
    const int mgrp = wid >> 1;
    const int nq   = wid & 1;

    // fragment lane geometry
    const int g  = lane >> 2;
    const int tq = lane & 3;
    const int b_ln = ((lane >> 4) << 3) + (lane & 7);
    const int b_ku = (lane >> 3) & 1;
    const int lane7 = lane & 7;
    const int R = mgrp * 32 + g;

    // ---- strength-reduced address bases ----
    const uint32_t prr = (uint32_t)(R & 1) << 6;
    const uint32_t c1r = (uint32_t)(lane7 >> 1) << 5;
    const uint32_t kb  = (uint32_t)(b_ku ^ (lane7 & 1)) << 4;
    uint32_t Bb[4];
    #pragma unroll
    for (int j = 0; j < 4; j++)
        Bb[j] = sb + SM_W + (uint32_t)(nq * 64 + b_ln) * 512u + (uint32_t)j * 8192u + kb;
    uint32_t Aoff[4];   // smem byte offsets of the 4 fragment rows (buf 0)
    #pragma unroll
    for (int i = 0; i < 4; i++)
        Aoff[i] = (uint32_t)XQ0 + (uint32_t)(R + 8 * i) * 256u + (uint32_t)tq * 16u;

    // staging constants
    const int row0 = tid >> 4, f4c = tid & 15;
    const uint32_t dstc = (uint32_t)XQ0 + (uint32_t)row0 * 256u
                        + ((uint32_t)(f4c ^ ((row0 & 1) << 2)) << 4);
    const float4* xf4 = (const float4*)x;

    auto issue_q = [&](int t, int q, int buf) {
        const int i0 = t * TILE_K;
        const float4* src = xf4 + (size_t)(i0 + row0) * 64 + q * 16 + f4c;
        uint32_t dst = sb + dstc + ((uint32_t)buf << 16);
        #pragma unroll
        for (int it = 0; it < 8; it++) {
            cp_async16z(dst, src, i0 + row0 + it * 32 < N_ITEMS_K);
            dst += 8192u;
            src += 2048;
        }
    };

    __syncthreads();   // W/b staged

    // ---- prologue: first tile quarters 0,1 ----
    issue_q(blockIdx.x, 0, 0); CP_COMMIT();
    issue_q(blockIdx.x, 1, 1); CP_COMMIT();

    for (int t = blockIdx.x; t < N_TILES_K; t += gridDim.x) {
        const int i0 = t * TILE_K;
        const int rows = min(TILE_K, N_ITEMS_K - i0);
        const int tn = t + gridDim.x;
        const int tnc = (tn < N_TILES_K) ? tn : t;   // clamped: redundant, unread
        int segreg = 0;
        if (tid < rows) segreg = seg[i0 + tid];

        float acc[2][8][4];
        #pragma unroll
        for (int m = 0; m < 2; m++)
            #pragma unroll
            for (int n = 0; n < 8; n++)
                #pragma unroll
                for (int i = 0; i < 4; i++) acc[m][n][i] = 0.f;

        auto compute_q = [&](uint32_t boff, uint32_t qoff) {
            #pragma unroll
            for (int s = 0; s < 4; s++) {
                const uint32_t offA = (((uint32_t)s << 6) ^ prr) + boff;
                const uint32_t offB = qoff + (((uint32_t)s << 5) ^ c1r);
                float4 v00 = *(const float4*)(sm + Aoff[0] + offA);
                float4 v01 = *(const float4*)(sm + Aoff[1] + offA);
                uint32_t B[4][4];
                ldsm4(B[0], Bb[0] + offB);
                ldsm4(B[1], Bb[1] + offB);
                ldsm4(B[2], Bb[2] + offB);
                ldsm4(B[3], Bb[3] + offB);
                float4 v10 = *(const float4*)(sm + Aoff[2] + offA);
                float4 v11 = *(const float4*)(sm + Aoff[3] + offA);

                uint32_t Ah[4];
                {
                    __half2 h0 = __float22half2_rn(make_float2(v00.x, v00.y));
                    __half2 h1 = __float22half2_rn(make_float2(v01.x, v01.y));
                    __half2 h2 = __float22half2_rn(make_float2(v00.z, v00.w));
                    __half2 h3 = __float22half2_rn(make_float2(v01.z, v01.w));
                    Ah[0] = *(uint32_t*)&h0; Ah[1] = *(uint32_t*)&h1;
                    Ah[2] = *(uint32_t*)&h2; Ah[3] = *(uint32_t*)&h3;
                }
                #pragma unroll
                for (int j = 0; j < 4; j++) {
                    mma16816(acc[0][2*j],   Ah, B[j][0], B[j][1]);
                    mma16816(acc[0][2*j+1], Ah, B[j][2], B[j][3]);
                }
                {
                    __half2 h0 = __float22half2_rn(make_float2(v10.x, v10.y));
                    __half2 h1 = __float22half2_rn(make_float2(v11.x, v11.y));
                    __half2 h2 = __float22half2_rn(make_float2(v10.z, v10.w));
                    __half2 h3 = __float22half2_rn(make_float2(v11.z, v11.w));
                    Ah[0] = *(uint32_t*)&h0; Ah[1] = *(uint32_t*)&h1;
                    Ah[2] = *(uint32_t*)&h2; Ah[3] = *(uint32_t*)&h3;
                }
                #pragma unroll
                for (int j = 0; j < 4; j++) {
                    mma16816(acc[1][2*j],   Ah, B[j][0], B[j][1]);
                    mma16816(acc[1][2*j+1], Ah, B[j][2], B[j][3]);
                }
            }
        };

        // ---- quarter schedule: refill at top of NEXT quarter (1 sync each) ----
        CP_WAIT1(); __syncthreads();
        compute_q(0, 0);
        CP_WAIT0(); __syncthreads();
        issue_q(t, 2, 0); CP_COMMIT();
        compute_q(1u << 16, 128);
        CP_WAIT0(); __syncthreads();
        issue_q(t, 3, 1); CP_COMMIT();
        compute_q(0, 256);
        CP_WAIT0(); __syncthreads();
        issue_q(tnc, 0, 0); CP_COMMIT();          // next tile q0 -> b0 (early!)
        compute_q(1u << 16, 384);
        __syncthreads();   // all q3 reads done before h overwrites b1

        // ---- epilogue: +b, relu, h (fp16) into b1 region ----
        {
            const int c0 = nq * 64 + 2 * tq;
            #pragma unroll
            for (int m = 0; m < 2; m++) {
                const int Rm = R + 16 * m;
                const uint32_t sw = (uint32_t)(g << 2);
                char* base0 = sm + SM_H16 + (size_t)Rm * 256;
                char* base1 = base0 + 8 * 256;
                #pragma unroll
                for (int n = 0; n < 8; n++) {
                    const int c = c0 + n * 8;
                    const uint32_t cp = (uint32_t)(c >> 1);
                    const float b0 = b_s[c], b1 = b_s[c + 1];
                    __half2 u0 = __float22half2_rn(make_float2(
                        fmaxf(acc[m][n][0] + b0, 0.f), fmaxf(acc[m][n][1] + b1, 0.f)));
                    __half2 u1 = __float22half2_rn(make_float2(
                        fmaxf(acc[m][n][2] + b0, 0.f), fmaxf(acc[m][n][3] + b1, 0.f)));
                    *(__half2*)(base0 + ((cp ^ sw) << 2)) = u0;
                    *(__half2*)(base1 + ((cp ^ sw) << 2)) = u1;
                }
            }
        }
        if (tid < rows) seg_s[tid] = segreg;
        __syncthreads();

        // ---- segment reduce: 4 row-groups (64 rows) x 128 columns ----
        {
            const int c    = tid & 127;
            const uint32_t cp = (uint32_t)(c >> 1);
            const uint32_t cb = (uint32_t)(c & 1) * 2u;
            const int r0   = (tid >> 7) * 64;
            const int rend = min(rows, r0 + 64);
            if (r0 < rows) {
                float a = 0.f;
                int cur = seg_s[r0];
                for (int r = r0; r < rend; r++) {
                    int s = seg_s[r];
                    if (s != cur) {
                        atomicAdd(&g_scratch[(size_t)cur * BAG_K + c], a);
                        a = 0.f;
                        cur = s;
                    }
                    const __half* hv = (const __half*)(sm + SM_H16 + (size_t)r * 256
                                     + (((cp ^ ((uint32_t)(r & 7) << 2)) << 2) + cb));
                    a += __half2float(*hv);
                }
                atomicAdd(&g_scratch[(size_t)cur * BAG_K + c], a);
            }
        }
        __syncthreads();   // h reads done before b1 refill

        issue_q(tnc, 1, 1); CP_COMMIT();          // next tile q1 -> b1
    }
}

// ---- per-column batch stats over the 50k bag means (vectorized) ----
__global__ void __launch_bounds__(256) stats_kernel(const int* __restrict__ blen)
{
    __shared__ float4 red_s[8][32];
    __shared__ float4 red_ss[8][32];
    const int c4 = threadIdx.x & 31;
    const int rs = threadIdx.x >> 5;
    float4 s  = make_float4(0.f, 0.f, 0.f, 0.f);
    float4 ss = make_float4(0.f, 0.f, 0.f, 0.f);
    const float4* gs = (const float4*)g_scratch;
    for (int r = blockIdx.x * 8 + rs; r < N_BAGS_K; r += gridDim.x * 8) {
        float inv = 1.f / (float)max(blen[r], 1);
        float4 v = gs[(size_t)r * 32 + c4];
        v.x *= inv; v.y *= inv; v.z *= inv; v.w *= inv;
        s.x += v.x;  s.y += v.y;  s.z += v.z;  s.w += v.w;
        ss.x += v.x * v.x; ss.y += v.y * v.y; ss.z += v.z * v.z; ss.w += v.w * v.w;
    }
    red_s[rs][c4]  = s;
    red_ss[rs][c4] = ss;
    __syncthreads();
    if (rs == 0) {
        #pragma unroll
        for (int i = 1; i < 8; i++) {
            float4 a = red_s[i][c4], b = red_ss[i][c4];
            s.x += a.x; s.y += a.y; s.z += a.z; s.w += a.w;
            ss.x += b.x; ss.y += b.y; ss.z += b.z; ss.w += b.w;
        }
        float* dst  = &g_scratch[(size_t)N_BAGS_K * BAG_K + c4 * 4];
        float* dst2 = &g_scratch[(size_t)N_BAGS_K * BAG_K + BAG_K + c4 * 4];
        atomicAdd(dst + 0, s.x);  atomicAdd(dst + 1, s.y);
        atomicAdd(dst + 2, s.z);  atomicAdd(dst + 3, s.w);
        atomicAdd(dst2 + 0, ss.x); atomicAdd(dst2 + 1, ss.y);
        atomicAdd(dst2 + 2, ss.z); atomicAdd(dst2 + 3, ss.w);
    }
}

// ---- normalize (vectorized) ----
__global__ void __launch_bounds__(256) norm_kernel(const int* __restrict__ blen,
                                                   const float* __restrict__ gamma,
                                                   const float* __restrict__ beta,
                                                   float* __restrict__ out)
{
    const int c4 = threadIdx.x & 31;
    const int rs = threadIdx.x >> 5;
    const float inv_n = 1.f / (float)N_BAGS_K;
    float4 m = *(const float4*)&g_scratch[(size_t)N_BAGS_K * BAG_K + c4 * 4];
    float4 e = *(const float4*)&g_scratch[(size_t)N_BAGS_K * BAG_K + BAG_K + c4 * 4];
    float4 ga = ((const float4*)gamma)[c4];
    float4 be = ((const float4*)beta)[c4];
    float4 mean, scale;
    mean.x = m.x * inv_n; mean.y = m.y * inv_n;
    mean.z = m.z * inv_n; mean.w = m.w * inv_n;
    scale.x = rsqrtf(e.x * inv_n - mean.x * mean.x + EPS_K) * ga.x;
    scale.y = rsqrtf(e.y * inv_n - mean.y * mean.y + EPS_K) * ga.y;
    scale.z = rsqrtf(e.z * inv_n - mean.z * mean.z + EPS_K) * ga.z;
    scale.w = rsqrtf(e.w * inv_n - mean.w * mean.w + EPS_K) * ga.w;
    const float4* gs = (const float4*)g_scratch;
    float4* o4 = (float4*)out;
    for (int r = blockIdx.x * 8 + rs; r < N_BAGS_K; r += gridDim.x * 8) {
        float inv = 1.f / (float)max(blen[r], 1);
        float4 v = gs[(size_t)r * 32 + c4];
        float4 o;
        o.x = (v.x * inv - mean.x) * scale.x + be.x;
        o.y = (v.y * inv - mean.y) * scale.y + be.y;
        o.z = (v.z * inv - mean.z) * scale.z + be.z;
        o.w = (v.w * inv - mean.w) * scale.w + be.w;
        o4[(size_t)r * 32 + c4] = o;
    }
}

extern "C" void kernel_launch(void* const* d_in, const int* in_sizes, int n_in,
                              void* d_out, int out_size)
{
    const float* x     = (const float*)d_in[0];
    const float* W     = (const float*)d_in[1];
    const float* bvec  = (const float*)d_in[2];
    const float* gamma = (const float*)d_in[3];
    const float* beta  = (const float*)d_in[4];
    const int*   seg   = (const int*)d_in[5];
    const int*   blen  = (const int*)d_in[6];
    float*       out   = (float*)d_out;

    (void)in_sizes; (void)n_in; (void)out_size;

    void* scratch = nullptr;
    cudaGetSymbolAddress(&scratch, g_scratch);
    cudaMemsetAsync(scratch, 0,
                    sizeof(float) * ((size_t)N_BAGS_K * BAG_K + 2 * BAG_K), 0);

    int dev = 0, nsm = 148;
    cudaGetDevice(&dev);
    cudaDeviceGetAttribute(&nsm, cudaDevAttrMultiProcessorCount, dev);

    cudaFuncSetAttribute(fused_gemm_seg_kernel,
                         cudaFuncAttributeMaxDynamicSharedMemorySize, SMEM_DYN);
    fused_gemm_seg_kernel<<<nsm, 512, SMEM_DYN>>>(x, W, bvec, seg);
    stats_kernel<<<256, 256>>>(blen);
    norm_kernel<<<1024, 256>>>(blen, gamma, beta, out);
}